// round 16
// baseline (speedup 1.0000x reference)
#include <cuda_runtime.h>
#include <cuda_bf16.h>
#include <math.h>
#include <stdint.h>

#define B_  32
#define T_  256
#define D_  1024
#define M_  256
#define S_  64
#define ROWS_ 2048
#define BT_  8192
#define ST  528
#define NCTA 128u

// smem layout (bytes)
#define AH_  0
#define AL_  8448
#define TH_  16896
#define TL_  25344
#define BH_  33792
#define BL_  67584
#define ZO_  101376
#define XO_  117760
#define PS_SMEM (XO_ + 2304)

// ---------------- static device scratch ----------------
__device__ float g_memP[2][(size_t)ROWS_ * M_];   // ping-pong raw memory
__device__ float g_ssP[2][ROWS_];                  // per-row sum-of-squares (parity)
__device__ float g_usage[2][ROWS_];                // parity usage
__device__ float g_mv[(size_t)BT_ * 512];
__device__ float g_vproj[(size_t)BT_ * 768];
__device__ float g_Wiv[(size_t)512 * D_];
__device__ float g_biv[512];
__device__ float g_Wx[(size_t)768 * M_];
__device__ __nv_bfloat16 g_Whh[(size_t)768 * M_];  // h-half weights bf16 hi [n][k]
__device__ __nv_bfloat16 g_Whl[(size_t)768 * M_];  // bf16 lo
__device__ float g_bx[768];
__device__ unsigned g_bar[T_];

__device__ __forceinline__ float sigm(float x) { return 1.f / (1.f + expf(-x)); }

__device__ __forceinline__ void hilo2(float x0, float x1, uint32_t& hw, uint32_t& lw)
{
    __nv_bfloat162 h, l;
    h.x = __float2bfloat16(x0); h.y = __float2bfloat16(x1);
    l.x = __float2bfloat16(x0 - __bfloat162float(h.x));
    l.y = __float2bfloat16(x1 - __bfloat162float(h.y));
    hw = *(uint32_t*)&h; lw = *(uint32_t*)&l;
}

#define MMA(acc, a0,a1,a2,a3, b0,b1) \
    asm volatile("mma.sync.aligned.m16n8k16.row.col.f32.bf16.bf16.f32 " \
        "{%0,%1,%2,%3}, {%4,%5,%6,%7}, {%8,%9}, {%0,%1,%2,%3};" \
        : "+f"((acc)[0]), "+f"((acc)[1]), "+f"((acc)[2]), "+f"((acc)[3]) \
        : "r"(a0), "r"(a1), "r"(a2), "r"(a3), "r"(b0), "r"(b1))

// grid-wide barrier (verified in R14: release + acquire-spin + post fences)
__device__ __forceinline__ void grid_bar(unsigned* ctr)
{
    __threadfence();
    __syncthreads();
    if (threadIdx.x == 0) {
        atomicAdd(ctr, 1u);
        unsigned v;
        do {
            asm volatile("ld.acquire.gpu.global.u32 %0, [%1];" : "=r"(v) : "l"(ctr) : "memory");
        } while (v < NCTA);
    }
    __syncthreads();
    __threadfence();
}

// ---------------- pack ----------------
__global__ void k_pack(const float* __restrict__ Wi, const float* __restrict__ bi,
                       const float* __restrict__ Wv, const float* __restrict__ bv,
                       const float* __restrict__ Wr, const float* __restrict__ br,
                       const float* __restrict__ Wz, const float* __restrict__ bz,
                       const float* __restrict__ Wu, const float* __restrict__ bu)
{
    int idx = blockIdx.x * blockDim.x + threadIdx.x;
    if (idx < 512 * 1024) {
        int r = idx >> 10, k = idx & 1023;
        g_Wiv[idx] = (r < 256) ? Wi[r * 1024 + k] : Wv[(r - 256) * 1024 + k];
    }
    if (idx < 768 * 256) {
        int n = idx >> 8, k = idx & 255;
        int gate = n >> 8, jj = n & 255;
        const float* Wg = (gate == 0) ? Wr : ((gate == 1) ? Wz : Wu);
        g_Wx[idx] = Wg[jj * 512 + k];
        float w = Wg[jj * 512 + 256 + k];
        __nv_bfloat16 h = __float2bfloat16(w);
        g_Whh[idx] = h;
        g_Whl[idx] = __float2bfloat16(w - __bfloat162float(h));
    }
    if (idx < 768) g_bx[idx] = (idx < 256) ? br[idx] : ((idx < 512) ? bz[idx - 256] : bu[idx - 512]);
    if (idx < 512) g_biv[idx] = (idx < 256) ? bi[idx] : bv[idx - 256];
}

// ---------------- init ----------------
__global__ void k_init(const float* __restrict__ mi)
{
    int row = blockIdx.x, tid = threadIdx.x;
    float v = 0.01f * mi[(size_t)row * M_ + tid];
    g_memP[0][(size_t)row * M_ + tid] = v;
    float ss = v * v;
    #pragma unroll
    for (int off = 16; off; off >>= 1) ss += __shfl_xor_sync(0xffffffffu, ss, off);
    __shared__ float wsum[8];
    if ((tid & 31) == 0) wsum[tid >> 5] = ss;
    __syncthreads();
    if (tid == 0) {
        g_ssP[0][row] = wsum[0] + wsum[1] + wsum[2] + wsum[3]
                      + wsum[4] + wsum[5] + wsum[6] + wsum[7];
        g_usage[0][row] = 0.f;
    }
    if (row == 0) g_bar[tid] = 0u;
}

// ---------------- precompute GEMMs (fp32, unchanged/passing) ----------------
template<int KTILE>
__device__ __forceinline__ void gemm_tile(const float* __restrict__ A, int lda,
                                          const float* __restrict__ W, int ldw,
                                          int K, int row0, int n0, float acc[4][4])
{
    __shared__ __align__(16) float sA[KTILE][68];
    __shared__ __align__(16) float sW[KTILE][68];
    const int tid = threadIdx.x;
    const int lr = tid >> 2, lk = (tid & 3) * 4;
    const int ty = tid >> 4, tx = tid & 15;
    for (int k0 = 0; k0 < K; k0 += KTILE) {
        float4 av = *(const float4*)(A + (size_t)(row0 + lr) * lda + k0 + lk);
        float4 wv = *(const float4*)(W + (size_t)(n0 + lr) * ldw + k0 + lk);
        __syncthreads();
        sA[lk + 0][lr] = av.x; sA[lk + 1][lr] = av.y; sA[lk + 2][lr] = av.z; sA[lk + 3][lr] = av.w;
        sW[lk + 0][lr] = wv.x; sW[lk + 1][lr] = wv.y; sW[lk + 2][lr] = wv.z; sW[lk + 3][lr] = wv.w;
        __syncthreads();
        #pragma unroll
        for (int kk = 0; kk < KTILE; kk++) {
            float4 a = *(const float4*)&sA[kk][ty * 4];
            float4 w = *(const float4*)&sW[kk][tx * 4];
            float ar[4] = {a.x, a.y, a.z, a.w};
            float wr[4] = {w.x, w.y, w.z, w.w};
            #pragma unroll
            for (int i = 0; i < 4; i++)
                #pragma unroll
                for (int j = 0; j < 4; j++)
                    acc[i][j] = fmaf(ar[i], wr[j], acc[i][j]);
        }
    }
}

__global__ void k_gemm_pre(const float* __restrict__ hidden, int mode)
{
    const float* A; const float* W; const float* bias; float* C;
    int lda, ldw, ldc, K, ntn;
    if (mode == 0) { A = hidden;     lda = 1024; W = g_Wiv; ldw = 1024; bias = g_biv; C = g_mv;    ldc = 512; K = 1024; ntn = 8;  }
    else           { A = g_mv + 256; lda = 512;  W = g_Wx;  ldw = 256;  bias = g_bx;  C = g_vproj; ldc = 768; K = 256;  ntn = 12; }
    int tr = blockIdx.x / ntn, tc = blockIdx.x % ntn;
    int row0 = tr * 64, n0 = tc * 64;
    float acc[4][4] = {};
    gemm_tile<16>(A, lda, W, ldw, K, row0, n0, acc);
    int ty = threadIdx.x >> 4, tx = threadIdx.x & 15;
    #pragma unroll
    for (int i = 0; i < 4; i++) {
        int r = row0 + ty * 4 + i;
        #pragma unroll
        for (int j = 0; j < 4; j++) {
            int n = n0 + tx * 4 + j;
            C[(size_t)r * ldc + n] = acc[i][j] + bias[n];
        }
    }
}

// ---------------- persistent kernel: 128 CTAs = 32 batches x 4 row-groups ----------------
__global__ void __launch_bounds__(256) k_persist()
{
    extern __shared__ __align__(16) char sm[];
    const int tid = threadIdx.x, wid = tid >> 5, lane = tid & 31;
    const int g = lane >> 2, q = lane & 3;
    const int b = blockIdx.x >> 2, rg = blockIdx.x & 3;
    const int rbase = b * 64 + rg * 16;          // first global row of this CTA
    float* sScl = (float*)(sm + XO_);            // 64
    float* sSco = (float*)(sm + XO_ + 256);      // 64
    float* sWw  = (float*)(sm + XO_ + 512);      // 64
    float* dvec = (float*)(sm + XO_ + 768);      // 256
    float* ssbuf= (float*)(sm + XO_ + 1792);     // [8][16]
    float* sZ   = (float*)(sm + ZO_);            // [16][256]

    const char* WHH = (const char*)g_Whh;
    const char* WHL = (const char*)g_Whl;

    uint4 pwh[8], pwl[8];
    const int brow = tid >> 2, bq = (tid & 3) * 128;   // stream: 64 W-rows/chunk, 128B quarters

    #pragma unroll 1
    for (int t = 0; t < T_; t++) {
        const float* memR = g_memP[t & 1];
        float*       memW = g_memP[(t + 1) & 1];
        const float* vpb  = g_vproj + ((size_t)(b * T_ + t)) * 768;

        // issue chunk 0 stream (rows 0..63 of W) early
        {
            const char* sh = WHH + (size_t)(0 * 64 + brow) * 512 + bq;
            const char* sl = WHL + (size_t)(0 * 64 + brow) * 512 + bq;
            #pragma unroll
            for (int i = 0; i < 8; i++) {
                pwh[i] = __ldcg((const uint4*)(sh + i * 16));
                pwl[i] = __ldcg((const uint4*)(sl + i * 16));
            }
        }
        if (tid < 64)
            sScl[tid] = 1.f / fmaxf(sqrtf(__ldcg(&g_ssP[t & 1][b * 64 + tid])), 1e-12f);
        dvec[tid] = g_mv[((size_t)(b * T_ + t)) * 512 + tid];
        __syncthreads();

        // A-build: own 16 rows mem_norm -> bf16 hi/lo
        {
            int row = tid >> 4, ke = (tid & 15) * 16;
            float scl = sScl[rg * 16 + row];
            const float* src = memR + (size_t)(rbase + row) * 256 + ke;
            char* dh = sm + AH_ + row * ST + ke * 2;
            char* dl = sm + AL_ + row * ST + ke * 2;
            #pragma unroll
            for (int i = 0; i < 4; i++) {
                float4 f = __ldcg((const float4*)(src + i * 4));
                uint32_t h0, l0, h1, l1;
                hilo2(f.x * scl, f.y * scl, h0, l0);
                hilo2(f.z * scl, f.w * scl, h1, l1);
                *(uint32_t*)(dh + i * 8) = h0; *(uint32_t*)(dh + i * 8 + 4) = h1;
                *(uint32_t*)(dl + i * 8) = l0; *(uint32_t*)(dl + i * 8 + 4) = l1;
            }
        }
        // sim over all 64 slots (redundant per CTA; deterministic)
        #pragma unroll
        for (int rr = 0; rr < 8; rr++) {
            int s = wid * 8 + rr;
            const float* mr = memR + (size_t)(b * 64 + s) * 256 + lane * 8;
            float4 m0 = __ldcg((const float4*)mr), m1 = __ldcg((const float4*)(mr + 4));
            float4 q0 = *(const float4*)&dvec[lane * 8], q1 = *(const float4*)&dvec[lane * 8 + 4];
            float p = m0.x * q0.x;
            p = fmaf(m0.y, q0.y, p); p = fmaf(m0.z, q0.z, p); p = fmaf(m0.w, q0.w, p);
            p = fmaf(m1.x, q1.x, p); p = fmaf(m1.y, q1.y, p);
            p = fmaf(m1.z, q1.z, p); p = fmaf(m1.w, q1.w, p);
            #pragma unroll
            for (int off = 16; off; off >>= 1) p += __shfl_xor_sync(0xffffffffu, p, off);
            if (lane == 0) sSco[s] = p;
        }
        __syncthreads();
        if (tid < 64) sSco[tid] = -sSco[tid] * sScl[tid] + 0.2f * __ldcg(&g_usage[t & 1][b * 64 + tid]);
        __syncthreads();
        if (tid < 32) {   // full warp 0: softmax over 64
            float x0 = sSco[tid], x1 = sSco[tid + 32];
            float mx = fmaxf(x0, x1);
            #pragma unroll
            for (int off = 16; off; off >>= 1) mx = fmaxf(mx, __shfl_xor_sync(0xffffffffu, mx, off));
            float e0 = expf(x0 - mx), e1 = expf(x1 - mx);
            float ssum = e0 + e1;
            #pragma unroll
            for (int off = 16; off; off >>= 1) ssum += __shfl_xor_sync(0xffffffffu, ssum, off);
            float inv = 1.f / ssum;
            sWw[tid] = e0 * inv; sWw[tid + 32] = e1 * inv;
        }
        __syncthreads();

        // -------- 12 chunks: 8 rz (cols 0..511) + 4 u (cols 512..767) --------
        float ssum0 = 0.f, ssum1 = 0.f;
        #pragma unroll 1
        for (int cc = 0; cc < 12; cc++) {
            __syncthreads();
            {   // store streamed chunk to B buffers
                char* dh = sm + BH_ + brow * ST + bq;
                char* dl = sm + BL_ + brow * ST + bq;
                #pragma unroll
                for (int i = 0; i < 8; i++) {
                    *(uint4*)(dh + i * 16) = pwh[i];
                    *(uint4*)(dl + i * 16) = pwl[i];
                }
            }
            __syncthreads();
            if (cc < 11) {
                const char* sh = WHH + (size_t)((cc + 1) * 64 + brow) * 512 + bq;
                const char* sl = WHL + (size_t)((cc + 1) * 64 + brow) * 512 + bq;
                #pragma unroll
                for (int i = 0; i < 8; i++) {
                    pwh[i] = __ldcg((const uint4*)(sh + i * 16));
                    pwl[i] = __ldcg((const uint4*)(sl + i * 16));
                }
            }
            // MMA: A(16x256) x B rows [wid*8 .. +8) -> warp tile 16x8
            const char* pAH = ((cc < 8) ? (sm + AH_) : (sm + TH_)) + g * ST + q * 4;
            const char* pAL = ((cc < 8) ? (sm + AL_) : (sm + TL_)) + g * ST + q * 4;
            const char* pBH = sm + BH_ + (wid * 8 + g) * ST + q * 4;
            const char* pBL = sm + BL_ + (wid * 8 + g) * ST + q * 4;
            float acc[4] = {0.f, 0.f, 0.f, 0.f};
            #pragma unroll
            for (int kc = 0; kc < 16; kc++) {
                const int kb = kc * 32;
                uint32_t ah0 = *(const uint32_t*)(pAH + kb);
                uint32_t ah1 = *(const uint32_t*)(pAH + kb + 8 * ST);
                uint32_t ah2 = *(const uint32_t*)(pAH + kb + 16);
                uint32_t ah3 = *(const uint32_t*)(pAH + kb + 8 * ST + 16);
                uint32_t al0 = *(const uint32_t*)(pAL + kb);
                uint32_t al1 = *(const uint32_t*)(pAL + kb + 8 * ST);
                uint32_t al2 = *(const uint32_t*)(pAL + kb + 16);
                uint32_t al3 = *(const uint32_t*)(pAL + kb + 8 * ST + 16);
                uint32_t bh0 = *(const uint32_t*)(pBH + kb);
                uint32_t bh1 = *(const uint32_t*)(pBH + kb + 16);
                uint32_t bl0 = *(const uint32_t*)(pBL + kb);
                uint32_t bl1 = *(const uint32_t*)(pBL + kb + 16);
                MMA(acc, ah0, ah1, ah2, ah3, bh0, bh1);
                MMA(acc, al0, al1, al2, al3, bh0, bh1);
                MMA(acc, ah0, ah1, ah2, ah3, bl0, bl1);
            }
            // epilogue for this warp's 16x8 tile; cols gcol, gcol+1
            const int gcol = cc * 64 + wid * 8 + 2 * q;
            float2 vp = *(const float2*)(vpb + gcol);
            const int row0 = g, row1 = g + 8;
            if (cc < 4) {          // r gate -> rm into T (hi/lo)
                float s0 = sScl[rg * 16 + row0], s1 = sScl[rg * 16 + row1];
                float2 m0 = __ldcg((const float2*)(memR + (size_t)(rbase + row0) * 256 + gcol));
                float2 m1 = __ldcg((const float2*)(memR + (size_t)(rbase + row1) * 256 + gcol));
                uint32_t h, l;
                hilo2(sigm(acc[0] + vp.x) * (m0.x * s0), sigm(acc[1] + vp.y) * (m0.y * s0), h, l);
                *(uint32_t*)(sm + TH_ + row0 * ST + gcol * 2) = h;
                *(uint32_t*)(sm + TL_ + row0 * ST + gcol * 2) = l;
                hilo2(sigm(acc[2] + vp.x) * (m1.x * s1), sigm(acc[3] + vp.y) * (m1.y * s1), h, l);
                *(uint32_t*)(sm + TH_ + row1 * ST + gcol * 2) = h;
                *(uint32_t*)(sm + TL_ + row1 * ST + gcol * 2) = l;
            } else if (cc < 8) {   // z gate -> sZ
                int zc = gcol - 256;
                float2 z0, z1;
                z0.x = sigm(acc[0] + vp.x); z0.y = sigm(acc[1] + vp.y);
                z1.x = sigm(acc[2] + vp.x); z1.y = sigm(acc[3] + vp.y);
                *(float2*)&sZ[row0 * 256 + zc] = z0;
                *(float2*)&sZ[row1 * 256 + zc] = z1;
            } else {               // u: blend into memW (own rows)
                int uc = gcol - 512;
                float s0 = sScl[rg * 16 + row0], s1 = sScl[rg * 16 + row1];
                float ww0 = sWw[rg * 16 + row0], ww1 = sWw[rg * 16 + row1];
                bool ok0 = ww0 > 0.01f, ok1 = ww1 > 0.01f;
                float w0 = ww0 * 0.5f, w1 = ww1 * 0.5f;
                float2 m0 = __ldcg((const float2*)(memR + (size_t)(rbase + row0) * 256 + uc));
                float2 m1 = __ldcg((const float2*)(memR + (size_t)(rbase + row1) * 256 + uc));
                float2 z0 = *(const float2*)&sZ[row0 * 256 + uc];
                float2 z1 = *(const float2*)&sZ[row1 * 256 + uc];
                float mv00 = m0.x * s0, mv01 = m0.y * s0;
                float mv10 = m1.x * s1, mv11 = m1.y * s1;
                float c00 = tanhf(acc[0] + vp.x), c01 = tanhf(acc[1] + vp.y);
                float c10 = tanhf(acc[2] + vp.x), c11 = tanhf(acc[3] + vp.y);
                float nh00 = (1.f - z0.x) * mv00 + z0.x * c00;
                float nh01 = (1.f - z0.y) * mv01 + z0.y * c01;
                float nh10 = (1.f - z1.x) * mv10 + z1.x * c10;
                float nh11 = (1.f - z1.y) * mv11 + z1.y * c11;
                float2 o0, o1;
                o0.x = ok0 ? (mv00 * (1.f - w0) + nh00 * w0) : m0.x;
                o0.y = ok0 ? (mv01 * (1.f - w0) + nh01 * w0) : m0.y;
                o1.x = ok1 ? (mv10 * (1.f - w1) + nh10 * w1) : m1.x;
                o1.y = ok1 ? (mv11 * (1.f - w1) + nh11 * w1) : m1.y;
                __stcg((float2*)(memW + (size_t)(rbase + row0) * 256 + uc), o0);
                __stcg((float2*)(memW + (size_t)(rbase + row1) * 256 + uc), o1);
                ssum0 = fmaf(o0.x, o0.x, fmaf(o0.y, o0.y, ssum0));
                ssum1 = fmaf(o1.x, o1.x, fmaf(o1.y, o1.y, ssum1));
            }
        }
        // ss row sums: quad-reduce (unconditional), per-warp partials, then combine
        ssum0 += __shfl_xor_sync(0xffffffffu, ssum0, 1);
        ssum0 += __shfl_xor_sync(0xffffffffu, ssum0, 2);
        ssum1 += __shfl_xor_sync(0xffffffffu, ssum1, 1);
        ssum1 += __shfl_xor_sync(0xffffffffu, ssum1, 2);
        if (q == 0) {
            ssbuf[wid * 16 + g] = ssum0;
            ssbuf[wid * 16 + g + 8] = ssum1;
        }
        __syncthreads();
        if (tid < 16) {
            float s = 0.f;
            #pragma unroll
            for (int w = 0; w < 8; w++) s += ssbuf[w * 16 + tid];
            __stcg(&g_ssP[(t + 1) & 1][rbase + tid], s);
            float w_ = sWw[rg * 16 + tid];
            __stcg(&g_usage[(t + 1) & 1][rbase + tid],
                   (__ldcg(&g_usage[t & 1][rbase + tid]) + (w_ > 0.01f ? w_ : 0.f)) * 0.99f);
        }
        grid_bar(&g_bar[t]);
    }
}

// ---------------- final normalize ----------------
__global__ void k_fin(float* __restrict__ out)
{
    int row = blockIdx.x, tid = threadIdx.x;
    __shared__ float sc;
    if (tid == 0)
        sc = 1.f / fmaxf(sqrtf(g_ssP[0][row]), 1e-12f);
    __syncthreads();
    out[(size_t)row * M_ + tid] = g_memP[0][(size_t)row * M_ + tid] * sc;
}

// ---------------- launch ----------------
extern "C" void kernel_launch(void* const* d_in, const int* in_sizes, int n_in,
                              void* d_out, int out_size)
{
    const float* hidden  = (const float*)d_in[0];
    const float* meminit = (const float*)d_in[1];
    const float* Wi = (const float*)d_in[2];
    const float* bi = (const float*)d_in[3];
    const float* Wv = (const float*)d_in[4];
    const float* bv = (const float*)d_in[5];
    const float* Wr = (const float*)d_in[6];
    const float* br = (const float*)d_in[7];
    const float* Wz = (const float*)d_in[8];
    const float* bz = (const float*)d_in[9];
    const float* Wu = (const float*)d_in[10];
    const float* bu = (const float*)d_in[11];

    static int attr_done = 0;
    if (!attr_done) {
        cudaFuncSetAttribute(k_persist, cudaFuncAttributeMaxDynamicSharedMemorySize, PS_SMEM);
        attr_done = 1;
    }

    k_pack<<<2048, 256>>>(Wi, bi, Wv, bv, Wr, br, Wz, bz, Wu, bu);
    k_init<<<ROWS_, 256>>>(meminit);
    k_gemm_pre<<<128 * 8, 256>>>(hidden, 0);
    k_gemm_pre<<<128 * 12, 256>>>(hidden, 1);
    k_persist<<<128, 256, PS_SMEM>>>();
    k_fin<<<ROWS_, 256>>>((float*)d_out);
}